// round 4
// baseline (speedup 1.0000x reference)
#include <cuda_runtime.h>
#include <cstdint>
#include <math.h>

#define T_SEQ 512
#define NB    256
#define KIN   300
#define HID   256

typedef unsigned long long ull;

// ---------------- static scratch (no allocations allowed) ----------------
__device__ float g_xp[(size_t)T_SEQ * NB * HID];   // xp[t][b][h], 128 MB
__device__ float g_hT[NB * HID];                   // final hidden state

// ---------------- packed dual-FP32 helpers (sm_10x f32x2 path) -----------
__device__ __forceinline__ ull fma2(ull a, ull b, ull c) {
    ull d;
    asm("fma.rn.f32x2 %0, %1, %2, %3;" : "=l"(d) : "l"(a), "l"(b), "l"(c));
    return d;
}
__device__ __forceinline__ float2 unpk(ull v) {
    float2 u;
    asm("mov.b64 {%0, %1}, %2;" : "=f"(u.x), "=f"(u.y) : "l"(v));
    return u;
}

// =========================================================================
// GEMM: g_xp[m][n] = sum_k x[m][k] * W_ih[n][k] + b_ih[n] + b_hh[n]
//   M = T_SEQ*NB = 131072, N = HID = 256, K = KIN = 300
//   Tile 128(m) x 64(n), K-chunk 12, 256 threads.
//   Thread grid: tn = tid&15 (fast, n -> coalesced stores), tm = tid>>4.
//   Each thread: 4 m-pairs x 4 n cols, f32x2 accumulators over the m-pair.
//   B tile stored duplicated so (b,b) pair = one LDS.64.
// =========================================================================
#define MT 128
#define NT 64
#define KC 12
#define NCHUNK 25   // 25*12 = 300 exactly

__global__ __launch_bounds__(256) void gemm_kernel(
    const float* __restrict__ A, const float* __restrict__ W,
    const float* __restrict__ b_ih, const float* __restrict__ b_hh)
{
    __shared__ __align__(16) float a_sh[2][KC * MT];
    __shared__ __align__(16) float b_sh[2][KC * NT * 2];

    const int tid = threadIdx.x;
    const int tn = tid & 15;
    const int tm = tid >> 4;
    const int m0 = blockIdx.x * MT;
    const int n0 = blockIdx.y * NT;

    // Per-thread global->smem assignments (constant across chunks).
    int aoff[6], asls[6];
#pragma unroll
    for (int j = 0; j < 6; ++j) {
        int idx = tid + 256 * j;           // 1536 = 128m x 12k
        int m = idx / KC, ki = idx - m * KC;
        aoff[j] = m * KIN + ki;
        asls[j] = ki * MT + m;
    }
    int boff[3], bsls[3];
#pragma unroll
    for (int j = 0; j < 3; ++j) {
        int idx = tid + 256 * j;           // 768 = 64n x 12k
        int n = idx / KC, ki = idx - n * KC;
        boff[j] = n * KIN + ki;
        bsls[j] = ki * (NT * 2) + 2 * n;
    }
    const float* Ab = A + (size_t)m0 * KIN;
    const float* Wb = W + (size_t)n0 * KIN;

    ull acc[4][4];
#pragma unroll
    for (int i = 0; i < 4; ++i)
#pragma unroll
        for (int j = 0; j < 4; ++j) acc[i][j] = 0ull;

    // Prologue: load chunk 0 into buffer 0.
    float aR[6], bR[3];
#pragma unroll
    for (int j = 0; j < 6; ++j) aR[j] = __ldg(Ab + aoff[j]);
#pragma unroll
    for (int j = 0; j < 3; ++j) bR[j] = __ldg(Wb + boff[j]);
#pragma unroll
    for (int j = 0; j < 6; ++j) a_sh[0][asls[j]] = aR[j];
#pragma unroll
    for (int j = 0; j < 3; ++j) { b_sh[0][bsls[j]] = bR[j]; b_sh[0][bsls[j] + 1] = bR[j]; }

    for (int c = 0; c < NCHUNK; ++c) {
        __syncthreads();                   // buf[c&1] ready; old readers done
        const int buf = c & 1;
        if (c + 1 < NCHUNK) {
            const int k0 = (c + 1) * KC;
#pragma unroll
            for (int j = 0; j < 6; ++j) aR[j] = __ldg(Ab + aoff[j] + k0);
#pragma unroll
            for (int j = 0; j < 3; ++j) bR[j] = __ldg(Wb + boff[j] + k0);
        }
#pragma unroll
        for (int ki = 0; ki < KC; ++ki) {
            const ull* ap = (const ull*)(a_sh[buf] + ki * MT);
            const ull* bp = (const ull*)(b_sh[buf] + ki * NT * 2);
            ull av[4], bv[4];
#pragma unroll
            for (int mp = 0; mp < 4; ++mp) av[mp] = ap[tm * 4 + mp];
#pragma unroll
            for (int nj = 0; nj < 4; ++nj) bv[nj] = bp[tn + 16 * nj];
#pragma unroll
            for (int mp = 0; mp < 4; ++mp)
#pragma unroll
                for (int nj = 0; nj < 4; ++nj)
                    acc[mp][nj] = fma2(av[mp], bv[nj], acc[mp][nj]);
        }
        if (c + 1 < NCHUNK) {
            const int nb = 1 - buf;
#pragma unroll
            for (int j = 0; j < 6; ++j) a_sh[nb][asls[j]] = aR[j];
#pragma unroll
            for (int j = 0; j < 3; ++j) { b_sh[nb][bsls[j]] = bR[j]; b_sh[nb][bsls[j] + 1] = bR[j]; }
        }
    }

    // Epilogue: add bias, store (lanes = tn fast -> coalesced 64B runs).
    float bias[4];
#pragma unroll
    for (int nj = 0; nj < 4; ++nj) {
        int cc = n0 + tn + 16 * nj;
        bias[nj] = __ldg(b_ih + cc) + __ldg(b_hh + cc);
    }
#pragma unroll
    for (int mp = 0; mp < 4; ++mp) {
        int r = m0 + tm * 8 + 2 * mp;
#pragma unroll
        for (int nj = 0; nj < 4; ++nj) {
            int cc = n0 + tn + 16 * nj;
            float2 u = unpk(acc[mp][nj]);
            g_xp[(size_t)r * HID + cc]       = u.x + bias[nj];
            g_xp[(size_t)(r + 1) * HID + cc] = u.y + bias[nj];
        }
    }
}

// =========================================================================
// Recurrent scan: 128 CTAs, each owns batches (2c, 2c+1), all 256 h-rows.
//   Thread tid = output row h. W_hh[tid][0:128) in 64 packed-f32x2 regs,
//   W_hh[tid][128:256) in 128 KB smem (k-major, conflict-free).
//   h double-buffered, interleaved (h0[k],h0[k+1],h1[k],h1[k+1]) so one
//   broadcast LDS.128 feeds both batches' k-pair fma2.
// =========================================================================
#define SCAN_SMEM (64 * 256 * (int)sizeof(float2) + 2 * 128 * (int)sizeof(float4))

__global__ __launch_bounds__(256, 1) void scan_kernel(const float* __restrict__ W_hh)
{
    extern __shared__ char smraw[];
    float2* w_sh = (float2*)smraw;                       // [64 kpairs][256 h]
    float4* h_sh = (float4*)(smraw + 64 * 256 * 8);      // [2 buf][128 kpairs]

    const int tid = threadIdx.x;
    const int b0 = blockIdx.x * 2, b1 = b0 + 1;

    // Register half of this thread's W_hh row (k in [0,128) as 64 pairs).
    ull wreg[64];
    const ull* wrow = (const ull*)(W_hh + tid * HID);
#pragma unroll
    for (int j = 0; j < 64; ++j) wreg[j] = __ldg(wrow + j);

    // Smem half (k in [128,256)), k-major so compute loads are conflict-free.
    const float2* wrow2 = (const float2*)(W_hh + tid * HID + 128);
    for (int j = 0; j < 64; ++j) w_sh[j * 256 + tid] = __ldg(wrow2 + j);

    if (tid < 128) h_sh[tid] = make_float4(0.f, 0.f, 0.f, 0.f);  // h = 0
    __syncthreads();

    const float* xp0 = g_xp + (size_t)b0 * HID + tid;
    const float* xp1 = g_xp + (size_t)b1 * HID + tid;

    float v0 = 0.f, v1 = 0.f;
    for (int t = 0; t < T_SEQ; ++t) {
        // Issue xp loads early; consumed only after the ~1000-cycle MAC loop.
        const float xv0 = __ldg(xp0 + (size_t)t * NB * HID);
        const float xv1 = __ldg(xp1 + (size_t)t * NB * HID);

        const ulonglong2* hb = (const ulonglong2*)(h_sh + (t & 1) * 128);
        ull acc0 = 0ull, acc1 = 0ull;
#pragma unroll
        for (int kp = 0; kp < 64; ++kp) {               // register-weight half
            ulonglong2 hv = hb[kp];                     // broadcast LDS.128
            acc0 = fma2(wreg[kp], hv.x, acc0);
            acc1 = fma2(wreg[kp], hv.y, acc1);
        }
#pragma unroll 16
        for (int kp = 0; kp < 64; ++kp) {               // smem-weight half
            ulonglong2 hv = hb[64 + kp];
            ull wv = *(const ull*)(w_sh + kp * 256 + tid);
            acc0 = fma2(wv, hv.x, acc0);
            acc1 = fma2(wv, hv.y, acc1);
        }
        float2 u0 = unpk(acc0), u1 = unpk(acc1);
        v0 = tanhf(u0.x + u0.y + xv0);
        v1 = tanhf(u1.x + u1.y + xv1);

        float* wb = (float*)(h_sh + ((t + 1) & 1) * 128);
        wb[(tid >> 1) * 4 + (tid & 1)]     = v0;
        wb[(tid >> 1) * 4 + 2 + (tid & 1)] = v1;
        __syncthreads();
    }
    g_hT[b0 * HID + tid] = v0;
    g_hT[b1 * HID + tid] = v1;
}

// =========================================================================
// Head: logits = hT @ W_fc^T + b_fc; out = log_softmax(logits)
// =========================================================================
__global__ void head_kernel(const float* __restrict__ W_fc,
                            const float* __restrict__ b_fc,
                            float* __restrict__ out)
{
    const int b = blockIdx.x, tid = threadIdx.x;   // 32 threads per block
    float s0 = 0.f, s1 = 0.f;
    for (int h = tid; h < HID; h += 32) {
        float hv = g_hT[b * HID + h];
        s0 += hv * __ldg(W_fc + h);
        s1 += hv * __ldg(W_fc + HID + h);
    }
#pragma unroll
    for (int off = 16; off; off >>= 1) {
        s0 += __shfl_xor_sync(0xffffffffu, s0, off);
        s1 += __shfl_xor_sync(0xffffffffu, s1, off);
    }
    if (tid == 0) {
        float l0 = s0 + __ldg(b_fc), l1 = s1 + __ldg(b_fc + 1);
        float m = fmaxf(l0, l1);
        float lse = m + logf(expf(l0 - m) + expf(l1 - m));
        out[2 * b]     = l0 - lse;
        out[2 * b + 1] = l1 - lse;
    }
}

// =========================================================================
extern "C" void kernel_launch(void* const* d_in, const int* in_sizes, int n_in,
                              void* d_out, int out_size)
{
    const float* x    = (const float*)d_in[0];
    const float* W_ih = (const float*)d_in[1];
    const float* W_hh = (const float*)d_in[2];
    const float* b_ih = (const float*)d_in[3];
    const float* b_hh = (const float*)d_in[4];
    const float* W_fc = (const float*)d_in[5];
    const float* b_fc = (const float*)d_in[6];
    float* out = (float*)d_out;

    cudaFuncSetAttribute(scan_kernel,
                         cudaFuncAttributeMaxDynamicSharedMemorySize, SCAN_SMEM);

    gemm_kernel<<<dim3(1024, 4, 1), 256>>>(x, W_ih, b_ih, b_hh);
    scan_kernel<<<128, 256, SCAN_SMEM>>>(W_hh);
    head_kernel<<<256, 32>>>(W_fc, b_fc, out);
}

// round 5
// speedup vs baseline: 1.6097x; 1.6097x over previous
#include <cuda_runtime.h>
#include <cstdint>
#include <math.h>

#define T_SEQ 512
#define NB    256
#define KIN   300
#define HID   256

typedef unsigned long long ull;

// ---------------- static scratch (no allocations allowed) ----------------
__device__ float g_xp[(size_t)T_SEQ * NB * HID];   // xp[t][b][h], 128 MB
__device__ float g_hT[NB * HID];                   // final hidden state

// ---------------- packed dual-FP32 helpers (sm_10x f32x2 path) -----------
__device__ __forceinline__ ull fma2(ull a, ull b, ull c) {
    ull d;
    asm("fma.rn.f32x2 %0, %1, %2, %3;" : "=l"(d) : "l"(a), "l"(b), "l"(c));
    return d;
}
__device__ __forceinline__ float2 unpk(ull v) {
    float2 u;
    asm("mov.b64 {%0, %1}, %2;" : "=f"(u.x), "=f"(u.y) : "l"(v));
    return u;
}

// =========================================================================
// GEMM: g_xp[m][n] = sum_k x[m][k] * W_ih[n][k] + b_ih[n] + b_hh[n]
//   M = 131072, N = 256, K = 300. Tile 128m x 64n, KC=12, 256 threads.
//   Warp grid 4m x 2n; thread: 2 m-pairs x 8 n. All operand reads LDS.128:
//     av = float4 (2 m-pairs), bv = dup-B float4 ((b,b),(b',b')).
//   5 LDS.128 -> 16 fma2 per thread-k  =>  FMA-pipe bound.
// =========================================================================
#define MT 128
#define NT 64
#define KC 12
#define NCHUNK 25   // 25*12 = 300 exactly

__global__ __launch_bounds__(256) void gemm_kernel(
    const float* __restrict__ A, const float* __restrict__ W,
    const float* __restrict__ b_ih, const float* __restrict__ b_hh)
{
    __shared__ __align__(16) float a_sh[2][KC * MT];
    __shared__ __align__(16) float b_sh[2][KC * NT * 2];

    const int tid  = threadIdx.x;
    const int lane = tid & 31;
    const int w    = tid >> 5;
    const int wm   = w & 3;        // 4 warp-rows  (32 m each)
    const int wn   = w >> 2;       // 2 warp-cols  (32 n each)
    const int lm   = lane & 7;     // 8 lanes along m
    const int ln   = lane >> 3;    // 4 lanes along n
    const int m0 = blockIdx.y * MT;
    const int n0 = blockIdx.x * NT;

    // Per-thread global->smem assignments (constant across chunks).
    int aoff[6], asls[6];
#pragma unroll
    for (int j = 0; j < 6; ++j) {
        int idx = tid + 256 * j;           // 1536 = 128m x 12k
        int m = idx / KC, ki = idx - m * KC;
        aoff[j] = m * KIN + ki;
        asls[j] = ki * MT + m;
    }
    int boff[3], bsls[3];
#pragma unroll
    for (int j = 0; j < 3; ++j) {
        int idx = tid + 256 * j;           // 768 = 64n x 12k
        int n = idx / KC, ki = idx - n * KC;
        boff[j] = n * KIN + ki;
        bsls[j] = ki * (NT * 2) + 2 * n;
    }
    const float* Ab = A + (size_t)m0 * KIN;
    const float* Wb = W + (size_t)n0 * KIN;

    ull acc[2][8];
#pragma unroll
    for (int i = 0; i < 2; ++i)
#pragma unroll
        for (int j = 0; j < 8; ++j) acc[i][j] = 0ull;

    // Prologue: load chunk 0 into buffer 0.
    float aR[6], bR[3];
#pragma unroll
    for (int j = 0; j < 6; ++j) aR[j] = __ldg(Ab + aoff[j]);
#pragma unroll
    for (int j = 0; j < 3; ++j) bR[j] = __ldg(Wb + boff[j]);
#pragma unroll
    for (int j = 0; j < 6; ++j) a_sh[0][asls[j]] = aR[j];
#pragma unroll
    for (int j = 0; j < 3; ++j) { b_sh[0][bsls[j]] = bR[j]; b_sh[0][bsls[j] + 1] = bR[j]; }

    const int a_fo = wm * 32 + lm * 4;           // float offset of this thread's float4 in a row
    const int b_fo = (wn * 16 + ln) * 4;         // base float offset in dup-B row (q adds 16 floats)

    for (int c = 0; c < NCHUNK; ++c) {
        __syncthreads();
        const int buf = c & 1;
        if (c + 1 < NCHUNK) {
            const int k0 = (c + 1) * KC;
#pragma unroll
            for (int j = 0; j < 6; ++j) aR[j] = __ldg(Ab + aoff[j] + k0);
#pragma unroll
            for (int j = 0; j < 3; ++j) bR[j] = __ldg(Wb + boff[j] + k0);
        }
#pragma unroll
        for (int ki = 0; ki < KC; ++ki) {
            const float* ab = a_sh[buf] + ki * MT;
            const float* bb = b_sh[buf] + ki * NT * 2;
            ulonglong2 av = *(const ulonglong2*)(ab + a_fo);   // .x = mpair0, .y = mpair1
            ulonglong2 bv[4];
#pragma unroll
            for (int q = 0; q < 4; ++q)
                bv[q] = *(const ulonglong2*)(bb + b_fo + q * 16);
#pragma unroll
            for (int q = 0; q < 4; ++q) {
                acc[0][2*q]   = fma2(av.x, bv[q].x, acc[0][2*q]);
                acc[0][2*q+1] = fma2(av.x, bv[q].y, acc[0][2*q+1]);
                acc[1][2*q]   = fma2(av.y, bv[q].x, acc[1][2*q]);
                acc[1][2*q+1] = fma2(av.y, bv[q].y, acc[1][2*q+1]);
            }
        }
        if (c + 1 < NCHUNK) {
            const int nb = 1 - buf;
#pragma unroll
            for (int j = 0; j < 6; ++j) a_sh[nb][asls[j]] = aR[j];
#pragma unroll
            for (int j = 0; j < 3; ++j) { b_sh[nb][bsls[j]] = bR[j]; b_sh[nb][bsls[j] + 1] = bR[j]; }
        }
    }

    // Epilogue: add bias, store float2 per (row, n-pair).
    float bias[8];
#pragma unroll
    for (int q = 0; q < 4; ++q) {
        int colb = n0 + wn * 32 + q * 8 + ln * 2;
        bias[2*q]   = __ldg(b_ih + colb)     + __ldg(b_hh + colb);
        bias[2*q+1] = __ldg(b_ih + colb + 1) + __ldg(b_hh + colb + 1);
    }
#pragma unroll
    for (int i = 0; i < 2; ++i) {
        int mp = wm * 16 + lm * 2 + i;
        int r  = m0 + 2 * mp;
#pragma unroll
        for (int q = 0; q < 4; ++q) {
            int colb = n0 + wn * 32 + q * 8 + ln * 2;
            float2 lo = unpk(acc[i][2*q]);     // (row r, row r+1) at col colb
            float2 hi = unpk(acc[i][2*q+1]);   // at col colb+1
            float2 s0 = make_float2(lo.x + bias[2*q], hi.x + bias[2*q+1]);
            float2 s1 = make_float2(lo.y + bias[2*q], hi.y + bias[2*q+1]);
            *(float2*)(g_xp + (size_t)r * HID + colb)       = s0;
            *(float2*)(g_xp + (size_t)(r + 1) * HID + colb) = s1;
        }
    }
}

// =========================================================================
// Recurrent scan: 128 CTAs, each owns batches (2c, 2c+1), 256 threads.
//   Thread t: rows r0 = t>>1 and r1 = r0+128;  k-half kh = t&1
//             (k in [kh*128, kh*128+128) = 64 k-pairs).
//   Weights: 48 k-pairs/row in registers (96 ull), 16 k-pairs/row in smem.
//   h double-buffered, interleaved (h0[k],h0[k+1],h1[k],h1[k+1]).
//   Per-warp crossbar: 64 broadcast LDS.128 (h) + 32 LDS.64x2ph (w)
//   = 128 phases = FMA floor. k-halves combined via shfl.xor(1); each lane
//   finalizes batch (t&1) for both rows -> no extra barrier.
// =========================================================================
#define SREG 48   // k-pairs per row in registers
#define SSM  16   // k-pairs per row in smem
#define SCAN_SMEM (2 * SSM * 256 * 8 + 2 * 128 * 16)   // 64KB weights + 4KB h

__global__ __launch_bounds__(256, 1) void scan_kernel(const float* __restrict__ W_hh)
{
    extern __shared__ char smraw[];
    float2* w_sh = (float2*)smraw;                        // [kh*SSM + j][256 rows]
    float4* h_sh = (float4*)(smraw + 2 * SSM * 256 * 8);  // [2 buf][128 kpairs]

    const int tid = threadIdx.x;
    const int r0  = tid >> 1;
    const int r1  = r0 + 128;
    const int kh  = tid & 1;            // k-half AND this lane's batch index
    const int bg  = blockIdx.x * 2 + kh;

    // Register weights: rows r0/r1, k-pairs [kh*64, kh*64+48).
    const float* base0 = W_hh + (size_t)r0 * HID + kh * 128;
    const float* base1 = W_hh + (size_t)r1 * HID + kh * 128;
    ull wa[SREG], wb[SREG];
#pragma unroll
    for (int j = 0; j < SREG; ++j) {
        wa[j] = __ldg((const ull*)base0 + j);
        wb[j] = __ldg((const ull*)base1 + j);
    }
    // Smem weights: k-pairs [kh*64+48, kh*64+64), row-indexed (conflict-spread).
#pragma unroll
    for (int j = 0; j < SSM; ++j) {
        w_sh[(kh * SSM + j) * 256 + r0] = __ldg((const float2*)base0 + SREG + j);
        w_sh[(kh * SSM + j) * 256 + r1] = __ldg((const float2*)base1 + SREG + j);
    }
    if (tid < 128) h_sh[tid] = make_float4(0.f, 0.f, 0.f, 0.f);   // h = 0
    __syncthreads();

    const float* xpb = g_xp + (size_t)bg * HID;

    float v0 = 0.f, v1 = 0.f;
    for (int t = 0; t < T_SEQ; ++t) {
        const float xv0 = __ldg(xpb + (size_t)t * NB * HID + r0);
        const float xv1 = __ldg(xpb + (size_t)t * NB * HID + r1);

        const ulonglong2* hb = (const ulonglong2*)(h_sh + (t & 1) * 128) + kh * 64;
        ull a00 = 0, a01 = 0, a10 = 0, a11 = 0;   // (row, batch)
#pragma unroll
        for (int j = 0; j < SREG; ++j) {
            ulonglong2 hv = hb[j];                 // .x = batch0 k-pair, .y = batch1
            a00 = fma2(wa[j], hv.x, a00);
            a01 = fma2(wa[j], hv.y, a01);
            a10 = fma2(wb[j], hv.x, a10);
            a11 = fma2(wb[j], hv.y, a11);
        }
#pragma unroll
        for (int j = 0; j < SSM; ++j) {
            ulonglong2 hv = hb[SREG + j];
            ull w0 = *(const ull*)(w_sh + (kh * SSM + j) * 256 + r0);
            ull w1 = *(const ull*)(w_sh + (kh * SSM + j) * 256 + r1);
            a00 = fma2(w0, hv.x, a00);
            a01 = fma2(w0, hv.y, a01);
            a10 = fma2(w1, hv.x, a10);
            a11 = fma2(w1, hv.y, a11);
        }
        // Horizontal sums for this k-half.
        float2 u;
        u = unpk(a00); float s00 = u.x + u.y;   // row0, batch0
        u = unpk(a01); float s01 = u.x + u.y;   // row0, batch1
        u = unpk(a10); float s10 = u.x + u.y;   // row1, batch0
        u = unpk(a11); float s11 = u.x + u.y;   // row1, batch1

        // Send partner (lane^1) the partials for ITS batch; keep my batch.
        float t0 = kh ? s00 : s01;               // row0, other batch
        float t1 = kh ? s10 : s11;               // row1, other batch
        float o0 = __shfl_xor_sync(0xffffffffu, t0, 1);
        float o1 = __shfl_xor_sync(0xffffffffu, t1, 1);
        float m0 = (kh ? s01 : s00) + o0;        // row0, my batch, full k sum
        float m1 = (kh ? s11 : s10) + o1;        // row1, my batch

        v0 = tanhf(m0 + xv0);
        v1 = tanhf(m1 + xv1);

        float* wbuf = (float*)(h_sh + ((t + 1) & 1) * 128);
        wbuf[(r0 >> 1) * 4 + (r0 & 1) + kh * 2] = v0;
        wbuf[(r1 >> 1) * 4 + (r1 & 1) + kh * 2] = v1;
        __syncthreads();
    }
    g_hT[bg * HID + r0] = v0;
    g_hT[bg * HID + r1] = v1;
}

// =========================================================================
// Head: logits = hT @ W_fc^T + b_fc; out = log_softmax(logits)
// =========================================================================
__global__ void head_kernel(const float* __restrict__ W_fc,
                            const float* __restrict__ b_fc,
                            float* __restrict__ out)
{
    const int b = blockIdx.x, tid = threadIdx.x;   // 32 threads per block
    float s0 = 0.f, s1 = 0.f;
    for (int h = tid; h < HID; h += 32) {
        float hv = g_hT[b * HID + h];
        s0 += hv * __ldg(W_fc + h);
        s1 += hv * __ldg(W_fc + HID + h);
    }
#pragma unroll
    for (int off = 16; off; off >>= 1) {
        s0 += __shfl_xor_sync(0xffffffffu, s0, off);
        s1 += __shfl_xor_sync(0xffffffffu, s1, off);
    }
    if (tid == 0) {
        float l0 = s0 + __ldg(b_fc), l1 = s1 + __ldg(b_fc + 1);
        float m = fmaxf(l0, l1);
        float lse = m + logf(expf(l0 - m) + expf(l1 - m));
        out[2 * b]     = l0 - lse;
        out[2 * b + 1] = l1 - lse;
    }
}

// =========================================================================
extern "C" void kernel_launch(void* const* d_in, const int* in_sizes, int n_in,
                              void* d_out, int out_size)
{
    const float* x    = (const float*)d_in[0];
    const float* W_ih = (const float*)d_in[1];
    const float* W_hh = (const float*)d_in[2];
    const float* b_ih = (const float*)d_in[3];
    const float* b_hh = (const float*)d_in[4];
    const float* W_fc = (const float*)d_in[5];
    const float* b_fc = (const float*)d_in[6];
    float* out = (float*)d_out;

    cudaFuncSetAttribute(scan_kernel,
                         cudaFuncAttributeMaxDynamicSharedMemorySize, SCAN_SMEM);

    gemm_kernel<<<dim3(4, 1024), 256>>>(x, W_ih, b_ih, b_hh);   // n fast -> A reuse in L2
    scan_kernel<<<128, 256, SCAN_SMEM>>>(W_hh);
    head_kernel<<<256, 32>>>(W_fc, b_fc, out);
}

// round 6
// speedup vs baseline: 2.0317x; 1.2622x over previous
#include <cuda_runtime.h>
#include <cstdint>
#include <math.h>

#define T_SEQ 512
#define NB    256
#define KIN   300
#define HID   256

typedef unsigned long long ull;

// ---------------- static scratch (no allocations allowed) ----------------
__device__ float g_xp[(size_t)T_SEQ * NB * HID];   // xp[t][b][h], 128 MB
__device__ float g_hT[NB * HID];                   // final hidden state

// ---------------- packed dual-FP32 helpers (sm_10x f32x2 path) -----------
__device__ __forceinline__ ull fma2(ull a, ull b, ull c) {
    ull d;
    asm("fma.rn.f32x2 %0, %1, %2, %3;" : "=l"(d) : "l"(a), "l"(b), "l"(c));
    return d;
}
__device__ __forceinline__ float2 unpk(ull v) {
    float2 u;
    asm("mov.b64 {%0, %1}, %2;" : "=f"(u.x), "=f"(u.y) : "l"(v));
    return u;
}

// =========================================================================
// GEMM (k-packed): g_xp[m][n] = sum_k x[m][k]*W_ih[n][k] + b_ih[n] + b_hh[n]
//   M = 131072, N = 256, K = 300. CTA tile 128m x 128n, KC = 12 (6 k-pairs).
//   Smem holds k-pair-packed ull: a_sh[kp][m] = (A[m][2kp], A[m][2kp+1]).
//   Thread tile 8m x 8n, acc[mi][ni] accumulates packed k-lanes; every
//   LDS.128 is per-lane distinct (no broadcast waste, no dup-B).
//   Per SM per k-pair: 256 crossbar phases vs 256 FMA cycles (1:1).
// =========================================================================
#define MT 128
#define NT 128
#define KC 12
#define KP 6
#define NCHUNK 25   // 25*12 = 300 exactly

__global__ __launch_bounds__(256, 1) void gemm_kernel(
    const float* __restrict__ A, const float* __restrict__ W,
    const float* __restrict__ b_ih, const float* __restrict__ b_hh)
{
    __shared__ __align__(16) ull a_sh[2][KP][160];   // m padded: m + (m>>3)*2
    __shared__ __align__(16) ull b_sh[2][KP][128];

    const int tid  = threadIdx.x;
    const int lane = tid & 31;
    const int w    = tid >> 5;
    const int wm   = w & 3;          // 4 warp-rows (32 m each)
    const int wn   = w >> 2;         // 2 warp-cols (64 n each)
    const int lm   = lane & 3;       // 4 lanes along m (8 m each)
    const int ln   = lane >> 2;      // 8 lanes along n (8 n each)
    const int m0 = blockIdx.y * MT;
    const int n0 = blockIdx.x * NT;

    // Writer mapping: 768 float2 per chunk for each of A/B -> 3 per thread.
    int aoff[3], asl[3], boff[3], bsl[3];
#pragma unroll
    for (int j = 0; j < 3; ++j) {
        int idx = tid + 256 * j;             // 768 = 128 rows x 6 kp
        int kp = idx % KP, row = idx / KP;
        aoff[j] = row * KIN + 2 * kp;
        asl[j]  = kp * 160 + row + (row >> 3) * 2;
        boff[j] = row * KIN + 2 * kp;
        bsl[j]  = kp * 128 + row;
    }
    const float* Ab = A + (size_t)m0 * KIN;
    const float* Wb = W + (size_t)n0 * KIN;

    ull acc[8][8];
#pragma unroll
    for (int i = 0; i < 8; ++i)
#pragma unroll
        for (int j = 0; j < 8; ++j) acc[i][j] = 0ull;

    // Prologue: chunk 0 -> buffer 0.
    float2 aR[3], bR[3];
#pragma unroll
    for (int j = 0; j < 3; ++j) {
        aR[j] = __ldg((const float2*)(Ab + aoff[j]));
        bR[j] = __ldg((const float2*)(Wb + boff[j]));
    }
    ull* a0 = &a_sh[0][0][0];
    ull* b0 = &b_sh[0][0][0];
#pragma unroll
    for (int j = 0; j < 3; ++j) {
        a0[asl[j]] = *(const ull*)&aR[j];
        b0[bsl[j]] = *(const ull*)&bR[j];
    }

    const int am   = wm * 32 + lm * 8;
    const int apad = am + (am >> 3) * 2;     // even -> 16B aligned
    const int bn   = wn * 64 + ln * 8;

    for (int c = 0; c < NCHUNK; ++c) {
        __syncthreads();
        const int buf = c & 1;
        if (c + 1 < NCHUNK) {
            const int k0 = (c + 1) * KC;
#pragma unroll
            for (int j = 0; j < 3; ++j) {
                aR[j] = __ldg((const float2*)(Ab + aoff[j] + k0));
                bR[j] = __ldg((const float2*)(Wb + boff[j] + k0));
            }
        }
#pragma unroll
        for (int kp = 0; kp < KP; ++kp) {
            const ulonglong2* ap = (const ulonglong2*)(&a_sh[buf][kp][apad]);
            const ulonglong2* bp = (const ulonglong2*)(&b_sh[buf][kp][bn]);
            ull av[8], bv[8];
#pragma unroll
            for (int i = 0; i < 4; ++i) {
                ulonglong2 t = ap[i]; av[2*i] = t.x; av[2*i+1] = t.y;
                ulonglong2 s = bp[i]; bv[2*i] = s.x; bv[2*i+1] = s.y;
            }
#pragma unroll
            for (int mi = 0; mi < 8; ++mi)
#pragma unroll
                for (int ni = 0; ni < 8; ++ni)
                    acc[mi][ni] = fma2(av[mi], bv[ni], acc[mi][ni]);
        }
        if (c + 1 < NCHUNK) {
            ull* an = &a_sh[1 - buf][0][0];
            ull* bnp = &b_sh[1 - buf][0][0];
#pragma unroll
            for (int j = 0; j < 3; ++j) {
                an[asl[j]]  = *(const ull*)&aR[j];
                bnp[bsl[j]] = *(const ull*)&bR[j];
            }
        }
    }

    // Epilogue: horizontal add of packed k-lanes + bias, float4 stores.
    float bias[8];
#pragma unroll
    for (int ni = 0; ni < 8; ++ni) {
        int cc = n0 + bn + ni;
        bias[ni] = __ldg(b_ih + cc) + __ldg(b_hh + cc);
    }
#pragma unroll
    for (int mi = 0; mi < 8; ++mi) {
        int row = m0 + am + mi;
        float o[8];
#pragma unroll
        for (int ni = 0; ni < 8; ++ni) {
            float2 u = unpk(acc[mi][ni]);
            o[ni] = u.x + u.y + bias[ni];
        }
        float* dst = g_xp + (size_t)row * HID + n0 + bn;
        *(float4*)dst       = make_float4(o[0], o[1], o[2], o[3]);
        *(float4*)(dst + 4) = make_float4(o[4], o[5], o[6], o[7]);
    }
}

// =========================================================================
// Recurrent scan: 128 CTAs x 256 threads, 2 batches per CTA.
//   lane layout: kh = lane>>4 (k-half AND batch), li = lane&15,
//                rows r0 = w*16+li, r1 = r0+128.
//   Weights: 44 k-pairs/row in regs (176 regs), 20 in smem (conflict-free
//   LDS.64: each 16-lane phase reads 128B contiguous).
//   h distribution: warp cooperatively loads all 128 h-entries
//   (4 conflict-free LDS.128/thread), then per k-pair j two double-shfls
//   deliver (b0 pair, b1 pair) -> zero crossbar broadcasts.
//   Partner (lane^16) holds the other k-half; combine via shfl.xor(16).
// =========================================================================
#define SREG 44
#define SSM  20
#define SCAN_SMEM (2 * SSM * 256 * 8 + 2 * 128 * 16)   // 80KB w + 4KB h

__global__ __launch_bounds__(256, 1) void scan_kernel(const float* __restrict__ W_hh)
{
    extern __shared__ char smraw[];
    ull* w_sh = (ull*)smraw;                               // [(kh*SSM+jj)*256 + r]
    double2* hbuf = (double2*)(smraw + 2 * SSM * 256 * 8); // [2][128]

    const int tid  = threadIdx.x;
    const int lane = tid & 31;
    const int w    = tid >> 5;
    const int kh   = lane >> 4;          // k-half AND batch index
    const int li   = lane & 15;
    const int r0   = w * 16 + li;        // [0,128)
    const int r1   = r0 + 128;
    const int bg   = blockIdx.x * 2 + kh;

    // Register weights: rows r0/r1, k-pairs [kh*64, kh*64+SREG).
    const ull* row0 = (const ull*)(W_hh + (size_t)r0 * HID + kh * 128);
    const ull* row1 = (const ull*)(W_hh + (size_t)r1 * HID + kh * 128);
    ull wa[SREG], wb[SREG];
#pragma unroll
    for (int j = 0; j < SREG; ++j) {
        wa[j] = __ldg(row0 + j);
        wb[j] = __ldg(row1 + j);
    }
    // Smem weights: remaining SSM k-pairs per row.
#pragma unroll
    for (int jj = 0; jj < SSM; ++jj) {
        w_sh[(kh * SSM + jj) * 256 + r0] = __ldg(row0 + SREG + jj);
        w_sh[(kh * SSM + jj) * 256 + r1] = __ldg(row1 + SREG + jj);
    }
    if (tid < 128) hbuf[tid] = make_double2(0.0, 0.0);   // h = 0 (buffer 0)
    __syncthreads();

    const float* xpb = g_xp + (size_t)bg * HID;

    float v0 = 0.f, v1 = 0.f;
    for (int t = 0; t < T_SEQ; ++t) {
        const float xv0 = __ldg(xpb + (size_t)t * NB * HID + r0);
        const float xv1 = __ldg(xpb + (size_t)t * NB * HID + r1);

        // Cooperative h load: lane l holds entries l, l+32, l+64, l+96.
        const double2* hb = hbuf + (t & 1) * 128;
        double2 hs0 = hb[lane];
        double2 hs1 = hb[lane + 32];
        double2 hs2 = hb[lane + 64];
        double2 hs3 = hb[lane + 96];

        ull a00 = 0, a01 = 0, a10 = 0, a11 = 0;   // (row, batch)
#pragma unroll
        for (int j = 0; j < 64; ++j) {
            const int src = ((2 * j) & 31) + kh;   // holder of entry 2j+kh
            const int q = j >> 4;                  // static under full unroll
            double dx = (q == 0) ? hs0.x : (q == 1) ? hs1.x : (q == 2) ? hs2.x : hs3.x;
            double dy = (q == 0) ? hs0.y : (q == 1) ? hs1.y : (q == 2) ? hs2.y : hs3.y;
            ull h0 = __double_as_longlong(__shfl_sync(0xffffffffu, dx, src)); // batch0 pair
            ull h1 = __double_as_longlong(__shfl_sync(0xffffffffu, dy, src)); // batch1 pair
            ull w0, w1;
            if (j < SREG) { w0 = wa[j]; w1 = wb[j]; }
            else {
                w0 = w_sh[(kh * SSM + (j - SREG)) * 256 + r0];
                w1 = w_sh[(kh * SSM + (j - SREG)) * 256 + r1];
            }
            a00 = fma2(w0, h0, a00);
            a01 = fma2(w0, h1, a01);
            a10 = fma2(w1, h0, a10);
            a11 = fma2(w1, h1, a11);
        }
        // Horizontal sums for this k-half.
        float2 u;
        u = unpk(a00); const float s00 = u.x + u.y;   // row0, batch0
        u = unpk(a01); const float s01 = u.x + u.y;   // row0, batch1
        u = unpk(a10); const float s10 = u.x + u.y;   // row1, batch0
        u = unpk(a11); const float s11 = u.x + u.y;   // row1, batch1

        // Exchange with partner (other k-half, lane^16): send its batch.
        const float t0 = kh ? s00 : s01;
        const float t1 = kh ? s10 : s11;
        const float o0 = __shfl_xor_sync(0xffffffffu, t0, 16);
        const float o1 = __shfl_xor_sync(0xffffffffu, t1, 16);
        const float m0v = (kh ? s01 : s00) + o0;
        const float m1v = (kh ? s11 : s10) + o1;

        v0 = tanhf(m0v + xv0);
        v1 = tanhf(m1v + xv1);

        // Write new h into next buffer's interleaved layout.
        float* nb = (float*)(hbuf + ((t + 1) & 1) * 128);
        const int base = (r0 >> 1) * 8 + 2 * kh + (r0 & 1);
        nb[base]     = v0;   // half 0 (k = r0)
        nb[base + 4] = v1;   // half 1 (k = r1)
        __syncthreads();
    }
    g_hT[bg * HID + r0] = v0;
    g_hT[bg * HID + r1] = v1;
}

// =========================================================================
// Head: logits = hT @ W_fc^T + b_fc; out = log_softmax(logits)
// =========================================================================
__global__ void head_kernel(const float* __restrict__ W_fc,
                            const float* __restrict__ b_fc,
                            float* __restrict__ out)
{
    const int b = blockIdx.x, tid = threadIdx.x;   // 32 threads per block
    float s0 = 0.f, s1 = 0.f;
    for (int h = tid; h < HID; h += 32) {
        float hv = g_hT[b * HID + h];
        s0 += hv * __ldg(W_fc + h);
        s1 += hv * __ldg(W_fc + HID + h);
    }
#pragma unroll
    for (int off = 16; off; off >>= 1) {
        s0 += __shfl_xor_sync(0xffffffffu, s0, off);
        s1 += __shfl_xor_sync(0xffffffffu, s1, off);
    }
    if (tid == 0) {
        float l0 = s0 + __ldg(b_fc), l1 = s1 + __ldg(b_fc + 1);
        float m = fmaxf(l0, l1);
        float lse = m + logf(expf(l0 - m) + expf(l1 - m));
        out[2 * b]     = l0 - lse;
        out[2 * b + 1] = l1 - lse;
    }
}

// =========================================================================
extern "C" void kernel_launch(void* const* d_in, const int* in_sizes, int n_in,
                              void* d_out, int out_size)
{
    const float* x    = (const float*)d_in[0];
    const float* W_ih = (const float*)d_in[1];
    const float* W_hh = (const float*)d_in[2];
    const float* b_ih = (const float*)d_in[3];
    const float* b_hh = (const float*)d_in[4];
    const float* W_fc = (const float*)d_in[5];
    const float* b_fc = (const float*)d_in[6];
    float* out = (float*)d_out;

    cudaFuncSetAttribute(scan_kernel,
                         cudaFuncAttributeMaxDynamicSharedMemorySize, SCAN_SMEM);

    gemm_kernel<<<dim3(2, 1024), 256>>>(x, W_ih, b_ih, b_hh);
    scan_kernel<<<128, 256, SCAN_SMEM>>>(W_hh);
    head_kernel<<<256, 32>>>(W_fc, b_fc, out);
}

// round 7
// speedup vs baseline: 2.3947x; 1.1786x over previous
#include <cuda_runtime.h>
#include <cstdint>
#include <math.h>

#define T_SEQ 512
#define NB    256
#define KIN   300
#define HID   256

typedef unsigned long long ull;

// ---------------- static scratch (no allocations allowed) ----------------
__device__ float g_xp[(size_t)T_SEQ * NB * HID];   // xp[t][b][h], 128 MB
__device__ float g_hT[NB * HID];                   // final hidden state

// ---------------- packed dual-FP32 helpers (sm_10x f32x2 path) -----------
__device__ __forceinline__ ull fma2(ull a, ull b, ull c) {
    ull d;
    asm("fma.rn.f32x2 %0, %1, %2, %3;" : "=l"(d) : "l"(a), "l"(b), "l"(c));
    return d;
}
__device__ __forceinline__ float2 unpk(ull v) {
    float2 u;
    asm("mov.b64 {%0, %1}, %2;" : "=f"(u.x), "=f"(u.y) : "l"(v));
    return u;
}

// =========================================================================
// GEMM (k-packed): g_xp[m][n] = sum_k x[m][k]*W_ih[n][k] + b_ih[n] + b_hh[n]
//   M = 131072, N = 256, K = 300. CTA tile 128m x 128n, KC = 20 (10 k-pairs),
//   15 chunks (fewer barriers; 2x longer prefetch window than KC=12).
//   Thread tile 8m x 8n over k-pair-packed ull smem; every operand read is
//   a conflict-free/broadcast LDS.128. Crossbar 256 ph == FMA 256 cyc /SM-kp.
// =========================================================================
#define MT 128
#define NT 128
#define KC 20
#define KP 10
#define NCHUNK 15   // 15*20 = 300 exactly
#define NLD 5       // 128 rows * 10 kp / 256 threads

__global__ __launch_bounds__(256, 1) void gemm_kernel(
    const float* __restrict__ A, const float* __restrict__ W,
    const float* __restrict__ b_ih, const float* __restrict__ b_hh)
{
    __shared__ __align__(16) ull a_sh[2][KP][160];   // m padded: m + (m>>3)*2
    __shared__ __align__(16) ull b_sh[2][KP][128];

    const int tid  = threadIdx.x;
    const int lane = tid & 31;
    const int w    = tid >> 5;
    const int wm   = w & 3;          // 4 warp-rows (32 m each)
    const int wn   = w >> 2;         // 2 warp-cols (64 n each)
    const int lm   = lane & 3;       // 4 lanes along m (8 m each)
    const int ln   = lane >> 2;      // 8 lanes along n (8 n each)
    const int m0 = blockIdx.y * MT;
    const int n0 = blockIdx.x * NT;

    // Writer mapping: 1280 float2 per chunk for each of A/B -> 5 per thread.
    int aoff[NLD], asl[NLD], boff[NLD], bsl[NLD];
#pragma unroll
    for (int j = 0; j < NLD; ++j) {
        int idx = tid + 256 * j;             // 1280 = 128 rows x 10 kp
        int kp = idx % KP, row = idx / KP;
        aoff[j] = row * KIN + 2 * kp;
        asl[j]  = kp * 160 + row + (row >> 3) * 2;
        boff[j] = row * KIN + 2 * kp;
        bsl[j]  = kp * 128 + row;
    }
    const float* Ab = A + (size_t)m0 * KIN;
    const float* Wb = W + (size_t)n0 * KIN;

    ull acc[8][8];
#pragma unroll
    for (int i = 0; i < 8; ++i)
#pragma unroll
        for (int j = 0; j < 8; ++j) acc[i][j] = 0ull;

    // Prologue: chunk 0 -> buffer 0.
    float2 aR[NLD], bR[NLD];
#pragma unroll
    for (int j = 0; j < NLD; ++j) {
        aR[j] = __ldg((const float2*)(Ab + aoff[j]));
        bR[j] = __ldg((const float2*)(Wb + boff[j]));
    }
    {
        ull* a0 = &a_sh[0][0][0];
        ull* b0 = &b_sh[0][0][0];
#pragma unroll
        for (int j = 0; j < NLD; ++j) {
            a0[asl[j]] = *(const ull*)&aR[j];
            b0[bsl[j]] = *(const ull*)&bR[j];
        }
    }

    const int am   = wm * 32 + lm * 8;
    const int apad = am + (am >> 3) * 2;     // even -> 16B aligned
    const int bn   = wn * 64 + ln * 8;

    for (int c = 0; c < NCHUNK; ++c) {
        __syncthreads();
        const int buf = c & 1;
        if (c + 1 < NCHUNK) {
            const int k0 = (c + 1) * KC;
#pragma unroll
            for (int j = 0; j < NLD; ++j) {
                aR[j] = __ldg((const float2*)(Ab + aoff[j] + k0));
                bR[j] = __ldg((const float2*)(Wb + boff[j] + k0));
            }
        }
#pragma unroll
        for (int kp = 0; kp < KP; ++kp) {
            const ulonglong2* ap = (const ulonglong2*)(&a_sh[buf][kp][apad]);
            const ulonglong2* bp = (const ulonglong2*)(&b_sh[buf][kp][bn]);
            ull av[8], bv[8];
#pragma unroll
            for (int i = 0; i < 4; ++i) {
                ulonglong2 t = ap[i]; av[2*i] = t.x; av[2*i+1] = t.y;
                ulonglong2 s = bp[i]; bv[2*i] = s.x; bv[2*i+1] = s.y;
            }
#pragma unroll
            for (int mi = 0; mi < 8; ++mi)
#pragma unroll
                for (int ni = 0; ni < 8; ++ni)
                    acc[mi][ni] = fma2(av[mi], bv[ni], acc[mi][ni]);
        }
        if (c + 1 < NCHUNK) {
            ull* an  = &a_sh[1 - buf][0][0];
            ull* bnp = &b_sh[1 - buf][0][0];
#pragma unroll
            for (int j = 0; j < NLD; ++j) {
                an[asl[j]]  = *(const ull*)&aR[j];
                bnp[bsl[j]] = *(const ull*)&bR[j];
            }
        }
    }

    // Epilogue: horizontal add of packed k-lanes + bias, float4 stores.
    float bias[8];
#pragma unroll
    for (int ni = 0; ni < 8; ++ni) {
        int cc = n0 + bn + ni;
        bias[ni] = __ldg(b_ih + cc) + __ldg(b_hh + cc);
    }
#pragma unroll
    for (int mi = 0; mi < 8; ++mi) {
        int row = m0 + am + mi;
        float o[8];
#pragma unroll
        for (int ni = 0; ni < 8; ++ni) {
            float2 u = unpk(acc[mi][ni]);
            o[ni] = u.x + u.y + bias[ni];
        }
        float* dst = g_xp + (size_t)row * HID + n0 + bn;
        *(float4*)dst       = make_float4(o[0], o[1], o[2], o[3]);
        *(float4*)(dst + 4) = make_float4(o[4], o[5], o[6], o[7]);
    }
}

// =========================================================================
// Recurrent scan: 128 CTAs x 256 threads, 2 batches per CTA.
//   Thread (g = tid&31, q = tid>>5): rows {g+32i, i<8}, k-pairs [16q,16q+16).
//   Weights: 10 kp/row in regs (80 ull), 6 kp/row in smem (conflict-free
//   LDS.64). h: 16 broadcast LDS.128/step (8-row reuse per 16B).
//   Partials reduced 8-way (over q) through smem; thread t finalizes row t
//   for both batches (tanh + h write). Two barriers per step.
// =========================================================================
#define WREG 10
#define SSM  6
#define WSH_BYTES  (8 * SSM * 8 * 32 * 8)        // 98304: smem weights
#define PART_BYTES (8 * 256 * 8)                 // 16384: partials (float2)
#define HBUF_BYTES (2 * 128 * 16)                // 4096:  h double buffer
#define SCAN_SMEM  (WSH_BYTES + PART_BYTES + HBUF_BYTES)

__global__ __launch_bounds__(256, 1) void scan_kernel(const float* __restrict__ W_hh)
{
    extern __shared__ char sm[];
    ull*    w_sh = (ull*)sm;
    float2* part = (float2*)(sm + WSH_BYTES);
    char*   hraw = sm + WSH_BYTES + PART_BYTES;

    const int tid = threadIdx.x;
    const int g   = tid & 31;
    const int q   = tid >> 5;
    const int bg  = blockIdx.x * 2;

    // Load weights: rows g+32i, k-pairs 16q+j.
    ull wreg[8][WREG];
#pragma unroll
    for (int i = 0; i < 8; ++i) {
        const ull* rp = (const ull*)(W_hh + (size_t)(g + 32 * i) * HID) + 16 * q;
#pragma unroll
        for (int j = 0; j < WREG; ++j) wreg[i][j] = __ldg(rp + j);
#pragma unroll
        for (int j2 = 0; j2 < SSM; ++j2)
            w_sh[((q * SSM + j2) * 8 + i) * 32 + g] = __ldg(rp + WREG + j2);
    }
    if (tid < 128) ((float4*)hraw)[tid] = make_float4(0.f, 0.f, 0.f, 0.f); // h=0, buf 0
    __syncthreads();

    float v0 = 0.f, v1 = 0.f;
    for (int t = 0; t < T_SEQ; ++t) {
        // xp for row tid, both batches (consumed after the long MAC loop).
        const float xv0 = __ldg(g_xp + (size_t)t * NB * HID + (size_t)bg * HID + tid);
        const float xv1 = __ldg(g_xp + (size_t)t * NB * HID + (size_t)(bg + 1) * HID + tid);

        const ulonglong2* hb = (const ulonglong2*)(hraw + (t & 1) * 2048) + 16 * q;
        ull a0[8], a1[8];
#pragma unroll
        for (int i = 0; i < 8; ++i) { a0[i] = 0ull; a1[i] = 0ull; }

#pragma unroll
        for (int j = 0; j < 16; ++j) {
            const ulonglong2 hv = hb[j];          // broadcast: (b0 pair, b1 pair)
            if (j < WREG) {
#pragma unroll
                for (int i = 0; i < 8; ++i) {
                    a0[i] = fma2(wreg[i][j], hv.x, a0[i]);
                    a1[i] = fma2(wreg[i][j], hv.y, a1[i]);
                }
            } else {
#pragma unroll
                for (int i = 0; i < 8; ++i) {
                    ull wv = w_sh[((q * SSM + (j - WREG)) * 8 + i) * 32 + g];
                    a0[i] = fma2(wv, hv.x, a0[i]);
                    a1[i] = fma2(wv, hv.y, a1[i]);
                }
            }
        }
        // Partial sums (this q's k-range) for 8 rows x 2 batches.
#pragma unroll
        for (int i = 0; i < 8; ++i) {
            float2 u0 = unpk(a0[i]), u1 = unpk(a1[i]);
            part[q * 256 + g + 32 * i] = make_float2(u0.x + u0.y, u1.x + u1.y);
        }
        __syncthreads();

        // Reduce over q: thread t owns row t, both batches.
        float s0 = xv0, s1 = xv1;
#pragma unroll
        for (int qq = 0; qq < 8; ++qq) {
            float2 p = part[qq * 256 + tid];
            s0 += p.x; s1 += p.y;
        }
        v0 = tanhf(s0);
        v1 = tanhf(s1);

        // Write new h (next buffer): entry kp = t>>1 holds [b0e,b0o,b1e,b1o].
        float* nb = (float*)(hraw + ((t + 1) & 1) * 2048);
        const int base = (tid >> 1) * 4 + (tid & 1);
        nb[base]     = v0;
        nb[base + 2] = v1;
        __syncthreads();
    }
    g_hT[(size_t)bg * HID + tid]       = v0;
    g_hT[(size_t)(bg + 1) * HID + tid] = v1;
}

// =========================================================================
// Head: logits = hT @ W_fc^T + b_fc; out = log_softmax(logits)
// =========================================================================
__global__ void head_kernel(const float* __restrict__ W_fc,
                            const float* __restrict__ b_fc,
                            float* __restrict__ out)
{
    const int b = blockIdx.x, tid = threadIdx.x;   // 32 threads per block
    float s0 = 0.f, s1 = 0.f;
    for (int h = tid; h < HID; h += 32) {
        float hv = g_hT[b * HID + h];
        s0 += hv * __ldg(W_fc + h);
        s1 += hv * __ldg(W_fc + HID + h);
    }
#pragma unroll
    for (int off = 16; off; off >>= 1) {
        s0 += __shfl_xor_sync(0xffffffffu, s0, off);
        s1 += __shfl_xor_sync(0xffffffffu, s1, off);
    }
    if (tid == 0) {
        float l0 = s0 + __ldg(b_fc), l1 = s1 + __ldg(b_fc + 1);
        float m = fmaxf(l0, l1);
        float lse = m + logf(expf(l0 - m) + expf(l1 - m));
        out[2 * b]     = l0 - lse;
        out[2 * b + 1] = l1 - lse;
    }
}

// =========================================================================
extern "C" void kernel_launch(void* const* d_in, const int* in_sizes, int n_in,
                              void* d_out, int out_size)
{
    const float* x    = (const float*)d_in[0];
    const float* W_ih = (const float*)d_in[1];
    const float* W_hh = (const float*)d_in[2];
    const float* b_ih = (const float*)d_in[3];
    const float* b_hh = (const float*)d_in[4];
    const float* W_fc = (const float*)d_in[5];
    const float* b_fc = (const float*)d_in[6];
    float* out = (float*)d_out;

    cudaFuncSetAttribute(scan_kernel,
                         cudaFuncAttributeMaxDynamicSharedMemorySize, SCAN_SMEM);

    gemm_kernel<<<dim3(2, 1024), 256>>>(x, W_ih, b_ih, b_hh);
    scan_kernel<<<128, 256, SCAN_SMEM>>>(W_hh);
    head_kernel<<<256, 32>>>(W_fc, b_fc, out);
}

// round 8
// speedup vs baseline: 2.5086x; 1.0476x over previous
#include <cuda_runtime.h>
#include <cstdint>
#include <math.h>

#define T_SEQ 512
#define NB    256
#define KIN   300
#define HID   256

typedef unsigned long long ull;

// ---------------- static scratch (no allocations allowed) ----------------
__device__ float g_xp[(size_t)T_SEQ * NB * HID];   // xp[t][b][h], 128 MB
__device__ float g_hT[NB * HID];                   // final hidden state

// ---------------- packed dual-FP32 helpers (sm_10x f32x2 path) -----------
__device__ __forceinline__ ull fma2(ull a, ull b, ull c) {
    ull d;
    asm("fma.rn.f32x2 %0, %1, %2, %3;" : "=l"(d) : "l"(a), "l"(b), "l"(c));
    return d;
}
__device__ __forceinline__ float2 unpk(ull v) {
    float2 u;
    asm("mov.b64 {%0, %1}, %2;" : "=f"(u.x), "=f"(u.y) : "l"(v));
    return u;
}

// =========================================================================
// GEMM (k-packed, 2 CTAs/SM): g_xp[m][n] = sum_k x[m][k]*W_ih[n][k] + bias
//   M = 131072, N = 256, K = 300. CTA tile 64m x 128n, 128 threads,
//   __launch_bounds__(128,2) -> 2 co-resident CTAs per SM so barrier and
//   prefetch holes in one CTA are covered by the other CTA's warps.
//   KC = 12 (6 k-pairs). Thread tile 8m x 8n over k-pair-packed ull smem.
// =========================================================================
#define MT 64
#define NT 128
#define KC 12
#define KP 6
#define NCHUNK 25   // 25*12 = 300 exactly
#define NLDA 3      // 64 rows  * 6 kp / 128 threads
#define NLDB 6      // 128 rows * 6 kp / 128 threads

__global__ __launch_bounds__(128, 2) void gemm_kernel(
    const float* __restrict__ A, const float* __restrict__ W,
    const float* __restrict__ b_ih, const float* __restrict__ b_hh)
{
    __shared__ __align__(16) ull a_sh[2][KP][80];    // m padded: m + (m>>3)*2
    __shared__ __align__(16) ull b_sh[2][KP][128];

    const int tid  = threadIdx.x;
    const int lane = tid & 31;
    const int w    = tid >> 5;
    const int wm   = w & 1;          // 2 warp-rows (32 m each)
    const int wn   = w >> 1;         // 2 warp-cols (64 n each)
    const int lm   = lane & 3;       // 4 lanes along m (8 m each)
    const int ln   = lane >> 2;      // 8 lanes along n (8 n each)
    const int m0 = blockIdx.y * MT;
    const int n0 = blockIdx.x * NT;

    // Writer mapping: A 384 float2/chunk, B 768 float2/chunk.
    int aoff[NLDA], asl[NLDA], boff[NLDB], bsl[NLDB];
#pragma unroll
    for (int j = 0; j < NLDA; ++j) {
        int idx = tid + 128 * j;             // 384 = 64 rows x 6 kp
        int kp = idx % KP, row = idx / KP;
        aoff[j] = row * KIN + 2 * kp;
        asl[j]  = kp * 80 + row + (row >> 3) * 2;
    }
#pragma unroll
    for (int j = 0; j < NLDB; ++j) {
        int idx = tid + 128 * j;             // 768 = 128 rows x 6 kp
        int kp = idx % KP, row = idx / KP;
        boff[j] = row * KIN + 2 * kp;
        bsl[j]  = kp * 128 + row;
    }
    const float* Ab = A + (size_t)m0 * KIN;
    const float* Wb = W + (size_t)n0 * KIN;

    ull acc[8][8];
#pragma unroll
    for (int i = 0; i < 8; ++i)
#pragma unroll
        for (int j = 0; j < 8; ++j) acc[i][j] = 0ull;

    // Prologue: chunk 0 -> buffer 0.
    float2 aR[NLDA], bR[NLDB];
#pragma unroll
    for (int j = 0; j < NLDA; ++j) aR[j] = __ldg((const float2*)(Ab + aoff[j]));
#pragma unroll
    for (int j = 0; j < NLDB; ++j) bR[j] = __ldg((const float2*)(Wb + boff[j]));
    {
        ull* a0 = &a_sh[0][0][0];
        ull* b0 = &b_sh[0][0][0];
#pragma unroll
        for (int j = 0; j < NLDA; ++j) a0[asl[j]] = *(const ull*)&aR[j];
#pragma unroll
        for (int j = 0; j < NLDB; ++j) b0[bsl[j]] = *(const ull*)&bR[j];
    }

    const int am   = wm * 32 + lm * 8;
    const int apad = am + (am >> 3) * 2;     // even -> 16B aligned
    const int bn   = wn * 64 + ln * 8;

    for (int c = 0; c < NCHUNK; ++c) {
        __syncthreads();
        const int buf = c & 1;
        if (c + 1 < NCHUNK) {
            const int k0 = (c + 1) * KC;
#pragma unroll
            for (int j = 0; j < NLDA; ++j) aR[j] = __ldg((const float2*)(Ab + aoff[j] + k0));
#pragma unroll
            for (int j = 0; j < NLDB; ++j) bR[j] = __ldg((const float2*)(Wb + boff[j] + k0));
        }
#pragma unroll
        for (int kp = 0; kp < KP; ++kp) {
            const ulonglong2* ap = (const ulonglong2*)(&a_sh[buf][kp][apad]);
            const ulonglong2* bp = (const ulonglong2*)(&b_sh[buf][kp][bn]);
            ull av[8], bv[8];
#pragma unroll
            for (int i = 0; i < 4; ++i) {
                ulonglong2 t = ap[i]; av[2*i] = t.x; av[2*i+1] = t.y;
                ulonglong2 s = bp[i]; bv[2*i] = s.x; bv[2*i+1] = s.y;
            }
#pragma unroll
            for (int mi = 0; mi < 8; ++mi)
#pragma unroll
                for (int ni = 0; ni < 8; ++ni)
                    acc[mi][ni] = fma2(av[mi], bv[ni], acc[mi][ni]);
        }
        if (c + 1 < NCHUNK) {
            ull* an  = &a_sh[1 - buf][0][0];
            ull* bnp = &b_sh[1 - buf][0][0];
#pragma unroll
            for (int j = 0; j < NLDA; ++j) an[asl[j]]  = *(const ull*)&aR[j];
#pragma unroll
            for (int j = 0; j < NLDB; ++j) bnp[bsl[j]] = *(const ull*)&bR[j];
        }
    }

    // Epilogue: horizontal add of packed k-lanes + bias, float4 stores.
    float bias[8];
#pragma unroll
    for (int ni = 0; ni < 8; ++ni) {
        int cc = n0 + bn + ni;
        bias[ni] = __ldg(b_ih + cc) + __ldg(b_hh + cc);
    }
#pragma unroll
    for (int mi = 0; mi < 8; ++mi) {
        int row = m0 + am + mi;
        float o[8];
#pragma unroll
        for (int ni = 0; ni < 8; ++ni) {
            float2 u = unpk(acc[mi][ni]);
            o[ni] = u.x + u.y + bias[ni];
        }
        float* dst = g_xp + (size_t)row * HID + n0 + bn;
        *(float4*)dst       = make_float4(o[0], o[1], o[2], o[3]);
        *(float4*)(dst + 4) = make_float4(o[4], o[5], o[6], o[7]);
    }
}

// =========================================================================
// Recurrent scan: 128 CTAs x 256 threads, 2 batches per CTA.
//   Thread (g = tid&31, q = tid>>5): rows {g+32i, i<8}, k-pairs [16q,16q+16).
//   Weights: 11 kp/row in regs, 5 kp/row in smem (conflict-free LDS.64).
//   h: 16 broadcast LDS.128/step. Partials reduced 8-way (over q) via smem;
//   thread t finalizes row t for both batches. Two barriers per step.
// =========================================================================
#define WREG 11
#define SSM  5
#define WSH_BYTES  (8 * SSM * 8 * 32 * 8)        // 81920: smem weights
#define PART_BYTES (8 * 256 * 8)                 // 16384: partials (float2)
#define HBUF_BYTES (2 * 128 * 16)                // 4096:  h double buffer
#define SCAN_SMEM  (WSH_BYTES + PART_BYTES + HBUF_BYTES)

__global__ __launch_bounds__(256, 1) void scan_kernel(const float* __restrict__ W_hh)
{
    extern __shared__ char sm[];
    ull*    w_sh = (ull*)sm;
    float2* part = (float2*)(sm + WSH_BYTES);
    char*   hraw = sm + WSH_BYTES + PART_BYTES;

    const int tid = threadIdx.x;
    const int g   = tid & 31;
    const int q   = tid >> 5;
    const int bg  = blockIdx.x * 2;

    // Load weights: rows g+32i, k-pairs 16q+j.
    ull wreg[8][WREG];
#pragma unroll
    for (int i = 0; i < 8; ++i) {
        const ull* rp = (const ull*)(W_hh + (size_t)(g + 32 * i) * HID) + 16 * q;
#pragma unroll
        for (int j = 0; j < WREG; ++j) wreg[i][j] = __ldg(rp + j);
#pragma unroll
        for (int j2 = 0; j2 < SSM; ++j2)
            w_sh[((q * SSM + j2) * 8 + i) * 32 + g] = __ldg(rp + WREG + j2);
    }
    if (tid < 128) ((float4*)hraw)[tid] = make_float4(0.f, 0.f, 0.f, 0.f); // h=0, buf 0
    __syncthreads();

    float v0 = 0.f, v1 = 0.f;
    for (int t = 0; t < T_SEQ; ++t) {
        // xp for row tid, both batches (consumed after the long MAC loop).
        const float xv0 = __ldg(g_xp + (size_t)t * NB * HID + (size_t)bg * HID + tid);
        const float xv1 = __ldg(g_xp + (size_t)t * NB * HID + (size_t)(bg + 1) * HID + tid);

        const ulonglong2* hb = (const ulonglong2*)(hraw + (t & 1) * 2048) + 16 * q;
        ull a0[8], a1[8];
#pragma unroll
        for (int i = 0; i < 8; ++i) { a0[i] = 0ull; a1[i] = 0ull; }

#pragma unroll
        for (int j = 0; j < 16; ++j) {
            const ulonglong2 hv = hb[j];          // broadcast: (b0 pair, b1 pair)
            if (j < WREG) {
#pragma unroll
                for (int i = 0; i < 8; ++i) {
                    a0[i] = fma2(wreg[i][j], hv.x, a0[i]);
                    a1[i] = fma2(wreg[i][j], hv.y, a1[i]);
                }
            } else {
#pragma unroll
                for (int i = 0; i < 8; ++i) {
                    ull wv = w_sh[((q * SSM + (j - WREG)) * 8 + i) * 32 + g];
                    a0[i] = fma2(wv, hv.x, a0[i]);
                    a1[i] = fma2(wv, hv.y, a1[i]);
                }
            }
        }
        // Partial sums (this q's k-range) for 8 rows x 2 batches.
#pragma unroll
        for (int i = 0; i < 8; ++i) {
            float2 u0 = unpk(a0[i]), u1 = unpk(a1[i]);
            part[q * 256 + g + 32 * i] = make_float2(u0.x + u0.y, u1.x + u1.y);
        }
        __syncthreads();

        // Reduce over q: thread t owns row t, both batches.
        float s0 = xv0, s1 = xv1;
#pragma unroll
        for (int qq = 0; qq < 8; ++qq) {
            float2 p = part[qq * 256 + tid];
            s0 += p.x; s1 += p.y;
        }
        v0 = tanhf(s0);
        v1 = tanhf(s1);

        // Write new h (next buffer): entry kp = t>>1 holds [b0e,b0o,b1e,b1o].
        float* nb = (float*)(hraw + ((t + 1) & 1) * 2048);
        const int base = (tid >> 1) * 4 + (tid & 1);
        nb[base]     = v0;
        nb[base + 2] = v1;
        __syncthreads();
    }
    g_hT[(size_t)bg * HID + tid]       = v0;
    g_hT[(size_t)(bg + 1) * HID + tid] = v1;
}

// =========================================================================
// Head: logits = hT @ W_fc^T + b_fc; out = log_softmax(logits)
// =========================================================================
__global__ void head_kernel(const float* __restrict__ W_fc,
                            const float* __restrict__ b_fc,
                            float* __restrict__ out)
{
    const int b = blockIdx.x, tid = threadIdx.x;   // 32 threads per block
    float s0 = 0.f, s1 = 0.f;
    for (int h = tid; h < HID; h += 32) {
        float hv = g_hT[b * HID + h];
        s0 += hv * __ldg(W_fc + h);
        s1 += hv * __ldg(W_fc + HID + h);
    }
#pragma unroll
    for (int off = 16; off; off >>= 1) {
        s0 += __shfl_xor_sync(0xffffffffu, s0, off);
        s1 += __shfl_xor_sync(0xffffffffu, s1, off);
    }
    if (tid == 0) {
        float l0 = s0 + __ldg(b_fc), l1 = s1 + __ldg(b_fc + 1);
        float m = fmaxf(l0, l1);
        float lse = m + logf(expf(l0 - m) + expf(l1 - m));
        out[2 * b]     = l0 - lse;
        out[2 * b + 1] = l1 - lse;
    }
}

// =========================================================================
extern "C" void kernel_launch(void* const* d_in, const int* in_sizes, int n_in,
                              void* d_out, int out_size)
{
    const float* x    = (const float*)d_in[0];
    const float* W_ih = (const float*)d_in[1];
    const float* W_hh = (const float*)d_in[2];
    const float* b_ih = (const float*)d_in[3];
    const float* b_hh = (const float*)d_in[4];
    const float* W_fc = (const float*)d_in[5];
    const float* b_fc = (const float*)d_in[6];
    float* out = (float*)d_out;

    cudaFuncSetAttribute(scan_kernel,
                         cudaFuncAttributeMaxDynamicSharedMemorySize, SCAN_SMEM);

    gemm_kernel<<<dim3(2, 2048), 128>>>(x, W_ih, b_ih, b_hh);
    scan_kernel<<<128, 256, SCAN_SMEM>>>(W_hh);
    head_kernel<<<256, 32>>>(W_fc, b_fc, out);
}

// round 10
// speedup vs baseline: 3.3891x; 1.3510x over previous
#include <cuda_runtime.h>
#include <cuda_bf16.h>
#include <cstdint>
#include <math.h>

#define T_SEQ 512
#define NB    256
#define KIN   300
#define HID   256

typedef unsigned long long ull;

// ---------------- static scratch (no allocations allowed) ----------------
__device__ float g_xp[(size_t)T_SEQ * NB * HID];   // xp[t][b][h], 128 MB
__device__ float g_hT[NB * HID];                   // final hidden state

// ---------------- packed dual-FP32 helpers (scan) ------------------------
__device__ __forceinline__ ull fma2(ull a, ull b, ull c) {
    ull d;
    asm("fma.rn.f32x2 %0, %1, %2, %3;" : "=l"(d) : "l"(a), "l"(b), "l"(c));
    return d;
}
__device__ __forceinline__ float2 unpk(ull v) {
    float2 u;
    asm("mov.b64 {%0, %1}, %2;" : "=f"(u.x), "=f"(u.y) : "l"(v));
    return u;
}

// ---------------- portable tensor-core helpers (sm_80+ mma.sync) ---------
__device__ __forceinline__ uint32_t smem_u32(const void* p) {
    uint32_t a;
    asm("{ .reg .u64 t; cvta.to.shared.u64 t, %1; cvt.u32.u64 %0, t; }" : "=r"(a) : "l"(p));
    return a;
}
__device__ __forceinline__ void ldsm4(uint32_t* r, uint32_t addr) {
    asm volatile("ldmatrix.sync.aligned.m8n8.x4.shared.b16 {%0,%1,%2,%3}, [%4];"
                 : "=r"(r[0]), "=r"(r[1]), "=r"(r[2]), "=r"(r[3]) : "r"(addr));
}
__device__ __forceinline__ void mma16816(float* c, const uint32_t* a,
                                         uint32_t b0, uint32_t b1) {
    asm volatile(
        "mma.sync.aligned.m16n8k16.row.col.f32.bf16.bf16.f32 "
        "{%0,%1,%2,%3}, {%4,%5,%6,%7}, {%8,%9}, {%0,%1,%2,%3};"
        : "+f"(c[0]), "+f"(c[1]), "+f"(c[2]), "+f"(c[3])
        : "r"(a[0]), "r"(a[1]), "r"(a[2]), "r"(a[3]), "r"(b0), "r"(b1));
}

// =========================================================================
// Tensor-core GEMM with bf16 split precision (HMMA, portable):
//   g_xp[m][n] = sum_k x[m][k]*W[n][k] + b_ih[n] + b_hh[n]
//   x = xh + xl, W = Wh + Wl (bf16); acc fp32 of xh*Wh + xh*Wl + xl*Wh.
//   CTA 128m x 128n, 8 warps (warp = 32m x 64n = 2x8 m16n8k16 tiles).
//   K chunks of 64 (5 chunks, tail zero-padded). Smem: 4 x 16KB bf16 tiles
//   (SW128-swizzled 128B rows) -> all ldmatrix.x4 conflict-free.
//   Single-buffer + 2 CTAs/SM for load/compute overlap.
// =========================================================================
#define AH_OFF 0
#define AL_OFF (16 * 1024)
#define WH_OFF (32 * 1024)
#define WL_OFF (48 * 1024)
#define GEMM_SMEM (64 * 1024)
#define NKCH 5

__device__ __forceinline__ void cvt_sts(float4 v, char* smem, uint32_t hi_off,
                                        uint32_t lo_off, uint32_t sw) {
    __nv_bfloat162 h01 = __float22bfloat162_rn(make_float2(v.x, v.y));
    __nv_bfloat162 h23 = __float22bfloat162_rn(make_float2(v.z, v.w));
    float2 f01 = __bfloat1622float2(h01);
    float2 f23 = __bfloat1622float2(h23);
    __nv_bfloat162 l01 = __float22bfloat162_rn(make_float2(v.x - f01.x, v.y - f01.y));
    __nv_bfloat162 l23 = __float22bfloat162_rn(make_float2(v.z - f23.x, v.w - f23.y));
    *(uint2*)(smem + hi_off + sw) = make_uint2(*(uint32_t*)&h01, *(uint32_t*)&h23);
    *(uint2*)(smem + lo_off + sw) = make_uint2(*(uint32_t*)&l01, *(uint32_t*)&l23);
}

__global__ __launch_bounds__(256, 2) void gemm_mma(
    const float* __restrict__ A, const float* __restrict__ W,
    const float* __restrict__ b_ih, const float* __restrict__ b_hh)
{
    extern __shared__ __align__(1024) char smem[];
    const uint32_t sbase = smem_u32(smem);
    const int tid  = threadIdx.x;
    const int lane = tid & 31;
    const int wid  = tid >> 5;
    const int wm   = wid & 3;        // 4 warp-rows (32 m)
    const int wn   = wid >> 2;       // 2 warp-cols (64 n)
    const int m0 = blockIdx.y * 128;
    const int n0 = blockIdx.x * 128;

    float acc[2][8][4];
#pragma unroll
    for (int i = 0; i < 2; ++i)
#pragma unroll
        for (int j = 0; j < 8; ++j)
#pragma unroll
            for (int r = 0; r < 4; ++r) acc[i][j][r] = 0.f;

    // ldmatrix per-lane address components.
    // A x4: mats (m0-7,k0-7),(m8-15,k0-7),(m0-7,k8-15),(m8-15,k8-15)
    const int a_row = wm * 32 + ((lane >> 3) & 1) * 8 + (lane & 7);  // + i*16
    const int a_kb  = (lane >> 4) * 8;                                // + k0
    // B x4: mats (n0-7,k0-7),(n0-7,k8-15),(n8-15,k0-7),(n8-15,k8-15)
    const int b_row = wn * 64 + (lane >> 4) * 8 + (lane & 7);         // + j2*16
    const int b_kb  = ((lane >> 3) & 1) * 8;                          // + k0

    for (int c = 0; c < NKCH; ++c) {
        const int k0g = c * 64;
        if (c) __syncthreads();   // all warps done reading previous chunk

        // ---- A tile: 128 x 64 fp32 -> hi/lo bf16 (8 float4/thread)
#pragma unroll
        for (int j = 0; j < 8; ++j) {
            int idx = tid + 256 * j;
            int row = idx >> 4, f4 = idx & 15;
            int colc = f4 * 4, colg = k0g + colc;
            float4 v = make_float4(0.f, 0.f, 0.f, 0.f);
            if (colg < KIN) v = __ldg((const float4*)(A + (size_t)(m0 + row) * KIN + colg));
            uint32_t bo = row * 128 + colc * 2;
            cvt_sts(v, smem, AH_OFF, AL_OFF, bo ^ ((bo >> 3) & 0x70));
        }
        // ---- W tile: 128 x 64 fp32 -> hi/lo bf16 (8 float4/thread)
#pragma unroll
        for (int j = 0; j < 8; ++j) {
            int idx = tid + 256 * j;
            int row = idx >> 4, f4 = idx & 15;
            int colc = f4 * 4, colg = k0g + colc;
            float4 v = make_float4(0.f, 0.f, 0.f, 0.f);
            if (colg < KIN) v = __ldg((const float4*)(W + (size_t)(n0 + row) * KIN + colg));
            uint32_t bo = row * 128 + colc * 2;
            cvt_sts(v, smem, WH_OFF, WL_OFF, bo ^ ((bo >> 3) & 0x70));
        }
        __syncthreads();

        // ---- consume: 3 products x 4 k16 steps x (2m x 8n) mma
#pragma unroll
        for (int p = 0; p < 3; ++p) {
            const uint32_t aoffp = (p < 2) ? AH_OFF : AL_OFF;
            const uint32_t woffp = (p == 1) ? WL_OFF : WH_OFF;
#pragma unroll
            for (int s = 0; s < 4; ++s) {
                const int k0 = s * 16;
                uint32_t af[2][4];
#pragma unroll
                for (int i = 0; i < 2; ++i) {
                    uint32_t bo = (a_row + i * 16) * 128 + (a_kb + k0) * 2;
                    ldsm4(af[i], sbase + aoffp + (bo ^ ((bo >> 3) & 0x70)));
                }
#pragma unroll
                for (int j2 = 0; j2 < 4; ++j2) {
                    uint32_t bf[4];
                    uint32_t bo = (b_row + j2 * 16) * 128 + (b_kb + k0) * 2;
                    ldsm4(bf, sbase + woffp + (bo ^ ((bo >> 3) & 0x70)));
#pragma unroll
                    for (int i = 0; i < 2; ++i) {
                        mma16816(acc[i][2 * j2],     af[i], bf[0], bf[1]);
                        mma16816(acc[i][2 * j2 + 1], af[i], bf[2], bf[3]);
                    }
                }
            }
        }
    }

    // ---- Epilogue: acc + bias -> g_xp (float2 per row/col-pair) ----------
    const int g = lane >> 2, tig = lane & 3;
#pragma unroll
    for (int j = 0; j < 8; ++j) {
        const int col = n0 + wn * 64 + j * 8 + 2 * tig;
        const float bb0 = __ldg(b_ih + col)     + __ldg(b_hh + col);
        const float bb1 = __ldg(b_ih + col + 1) + __ldg(b_hh + col + 1);
#pragma unroll
        for (int i = 0; i < 2; ++i) {
            const int row = m0 + wm * 32 + i * 16 + g;
            *(float2*)(g_xp + (size_t)row * HID + col) =
                make_float2(acc[i][j][0] + bb0, acc[i][j][1] + bb1);
            *(float2*)(g_xp + (size_t)(row + 8) * HID + col) =
                make_float2(acc[i][j][2] + bb0, acc[i][j][3] + bb1);
        }
    }
}

// =========================================================================
// Recurrent scan (unchanged): 128 CTAs x 256 threads, 2 batches/CTA.
// =========================================================================
#define WREG 11
#define SSM  5
#define WSH_BYTES  (8 * SSM * 8 * 32 * 8)
#define PART_BYTES (8 * 256 * 8)
#define HBUF_BYTES (2 * 128 * 16)
#define SCAN_SMEM  (WSH_BYTES + PART_BYTES + HBUF_BYTES)

__global__ __launch_bounds__(256, 1) void scan_kernel(const float* __restrict__ W_hh)
{
    extern __shared__ char sm[];
    ull*    w_sh = (ull*)sm;
    float2* part = (float2*)(sm + WSH_BYTES);
    char*   hraw = sm + WSH_BYTES + PART_BYTES;

    const int tid = threadIdx.x;
    const int g   = tid & 31;
    const int q   = tid >> 5;
    const int bg  = blockIdx.x * 2;

    ull wreg[8][WREG];
#pragma unroll
    for (int i = 0; i < 8; ++i) {
        const ull* rp = (const ull*)(W_hh + (size_t)(g + 32 * i) * HID) + 16 * q;
#pragma unroll
        for (int j = 0; j < WREG; ++j) wreg[i][j] = __ldg(rp + j);
#pragma unroll
        for (int j2 = 0; j2 < SSM; ++j2)
            w_sh[((q * SSM + j2) * 8 + i) * 32 + g] = __ldg(rp + WREG + j2);
    }
    if (tid < 128) ((float4*)hraw)[tid] = make_float4(0.f, 0.f, 0.f, 0.f);
    __syncthreads();

    float v0 = 0.f, v1 = 0.f;
    for (int t = 0; t < T_SEQ; ++t) {
        const float xv0 = __ldg(g_xp + (size_t)t * NB * HID + (size_t)bg * HID + tid);
        const float xv1 = __ldg(g_xp + (size_t)t * NB * HID + (size_t)(bg + 1) * HID + tid);

        const ulonglong2* hb = (const ulonglong2*)(hraw + (t & 1) * 2048) + 16 * q;
        ull a0[8], a1[8];
#pragma unroll
        for (int i = 0; i < 8; ++i) { a0[i] = 0ull; a1[i] = 0ull; }

#pragma unroll
        for (int j = 0; j < 16; ++j) {
            const ulonglong2 hv = hb[j];
            if (j < WREG) {
#pragma unroll
                for (int i = 0; i < 8; ++i) {
                    a0[i] = fma2(wreg[i][j], hv.x, a0[i]);
                    a1[i] = fma2(wreg[i][j], hv.y, a1[i]);
                }
            } else {
#pragma unroll
                for (int i = 0; i < 8; ++i) {
                    ull wv = w_sh[((q * SSM + (j - WREG)) * 8 + i) * 32 + g];
                    a0[i] = fma2(wv, hv.x, a0[i]);
                    a1[i] = fma2(wv, hv.y, a1[i]);
                }
            }
        }
#pragma unroll
        for (int i = 0; i < 8; ++i) {
            float2 u0 = unpk(a0[i]), u1 = unpk(a1[i]);
            part[q * 256 + g + 32 * i] = make_float2(u0.x + u0.y, u1.x + u1.y);
        }
        __syncthreads();

        float s0 = xv0, s1 = xv1;
#pragma unroll
        for (int qq = 0; qq < 8; ++qq) {
            float2 p = part[qq * 256 + tid];
            s0 += p.x; s1 += p.y;
        }
        v0 = tanhf(s0);
        v1 = tanhf(s1);

        float* nb = (float*)(hraw + ((t + 1) & 1) * 2048);
        const int base = (tid >> 1) * 4 + (tid & 1);
        nb[base]     = v0;
        nb[base + 2] = v1;
        __syncthreads();
    }
    g_hT[(size_t)bg * HID + tid]       = v0;
    g_hT[(size_t)(bg + 1) * HID + tid] = v1;
}

// =========================================================================
// Head: logits = hT @ W_fc^T + b_fc; out = log_softmax(logits)
// =========================================================================
__global__ void head_kernel(const float* __restrict__ W_fc,
                            const float* __restrict__ b_fc,
                            float* __restrict__ out)
{
    const int b = blockIdx.x, tid = threadIdx.x;
    float s0 = 0.f, s1 = 0.f;
    for (int h = tid; h < HID; h += 32) {
        float hv = g_hT[b * HID + h];
        s0 += hv * __ldg(W_fc + h);
        s1 += hv * __ldg(W_fc + HID + h);
    }
#pragma unroll
    for (int off = 16; off; off >>= 1) {
        s0 += __shfl_xor_sync(0xffffffffu, s0, off);
        s1 += __shfl_xor_sync(0xffffffffu, s1, off);
    }
    if (tid == 0) {
        float l0 = s0 + __ldg(b_fc), l1 = s1 + __ldg(b_fc + 1);
        float m = fmaxf(l0, l1);
        float lse = m + logf(expf(l0 - m) + expf(l1 - m));
        out[2 * b]     = l0 - lse;
        out[2 * b + 1] = l1 - lse;
    }
}

// =========================================================================
extern "C" void kernel_launch(void* const* d_in, const int* in_sizes, int n_in,
                              void* d_out, int out_size)
{
    const float* x    = (const float*)d_in[0];
    const float* W_ih = (const float*)d_in[1];
    const float* W_hh = (const float*)d_in[2];
    const float* b_ih = (const float*)d_in[3];
    const float* b_hh = (const float*)d_in[4];
    const float* W_fc = (const float*)d_in[5];
    const float* b_fc = (const float*)d_in[6];
    float* out = (float*)d_out;

    cudaFuncSetAttribute(gemm_mma,
                         cudaFuncAttributeMaxDynamicSharedMemorySize, GEMM_SMEM);
    cudaFuncSetAttribute(scan_kernel,
                         cudaFuncAttributeMaxDynamicSharedMemorySize, SCAN_SMEM);

    gemm_mma<<<dim3(2, 1024), 256, GEMM_SMEM>>>(x, W_ih, b_ih, b_hh);
    scan_kernel<<<128, 256, SCAN_SMEM>>>(W_hh);
    head_kernel<<<256, 32>>>(W_fc, b_fc, out);
}